// round 1
// baseline (speedup 1.0000x reference)
#include <cuda_runtime.h>
#include <cuda_bf16.h>
#include <math.h>

// Problem dims (fixed per reference)
#define BB 2
#define LL 1024
#define DM 1024
#define DS 16
#define DC 4
#define DI 2048
#define MR (BB*LL)          // 2048 rows
#define NXZ (2*DI)          // 4096
#define NSSM (2*DS+DI)      // 2080

// Scratch (device globals; allocation inside kernel_launch is forbidden)
__device__ float g_xz [MR*NXZ];    // 32 MB : [x_inner | z]
__device__ float g_u  [MR*DI];     // 16 MB : silu(conv(x_inner))
__device__ float g_ssm[MR*NSSM];   // 17 MB : [B(16) | C(16) | dt_in(2048)]
__device__ float g_dt [MR*DI];     // 16 MB : softplus(dt_in @ Wdt + b)
__device__ float g_y  [MR*DI];     // 16 MB : scan output, then gated

__device__ __forceinline__ float siluf(float x) {
    return x / (1.0f + __expf(-x));
}
__device__ __forceinline__ float softplusf(float x) {
    // stable: max(x,0) + log1p(exp(-|x|))
    return fmaxf(x, 0.0f) + log1pf(__expf(-fabsf(x)));
}

// ---------------------------------------------------------------------------
// Tiled SGEMM: C[M,N] = A[M,K] @ B[K,N], row-major with leading dims.
// BM=BN=128, BK=8, 256 threads, 8x8 micro-tile.
// EPI==1: C = softplus(C + bias[col])
// Assumes: M % 128 == 0, K % 8 == 0, N % 4 == 0 (true for all calls here).
// ---------------------------------------------------------------------------
#define GBM 128
#define GBN 128
#define GBK 8

template<int EPI>
__global__ __launch_bounds__(256, 1)
void sgemm_kernel(const float* __restrict__ A, int lda,
                  const float* __restrict__ Bm, int ldb,
                  float* __restrict__ C, int ldc,
                  int M, int N, int K,
                  const float* __restrict__ bias)
{
    __shared__ float As[GBK][GBM];
    __shared__ float Bs[GBK][GBN];

    const int tid = threadIdx.x;            // 0..255
    const int row0 = blockIdx.y * GBM;
    const int col0 = blockIdx.x * GBN;

    // A tile load: 128x8 floats = 256 float4; thread -> (row tid/2, col (tid&1)*4)
    const int arow = tid >> 1;
    const int acol = (tid & 1) * 4;
    // B tile load: 8x128 floats = 256 float4; thread -> (row tid/32, col (tid&31)*4)
    const int brow = tid >> 5;
    const int bcol = (tid & 31) * 4;

    const int ty = tid >> 4;   // 0..15
    const int tx = tid & 15;   // 0..15

    float acc[8][8];
    #pragma unroll
    for (int i = 0; i < 8; i++)
        #pragma unroll
        for (int j = 0; j < 8; j++) acc[i][j] = 0.0f;

    for (int k0 = 0; k0 < K; k0 += GBK) {
        // load A (always in-bounds: M,K multiples of tile)
        float4 av = *reinterpret_cast<const float4*>(
            A + (size_t)(row0 + arow) * lda + (k0 + acol));
        As[acol + 0][arow] = av.x;
        As[acol + 1][arow] = av.y;
        As[acol + 2][arow] = av.z;
        As[acol + 3][arow] = av.w;

        // load B (guard N edge; N % 4 == 0 so float4 fully in or out)
        float4 bv;
        if (col0 + bcol < N) {
            bv = *reinterpret_cast<const float4*>(
                Bm + (size_t)(k0 + brow) * ldb + (col0 + bcol));
        } else {
            bv = make_float4(0.f, 0.f, 0.f, 0.f);
        }
        *reinterpret_cast<float4*>(&Bs[brow][bcol]) = bv;

        __syncthreads();

        #pragma unroll
        for (int k = 0; k < GBK; k++) {
            float a[8], b[8];
            float4 a0 = *reinterpret_cast<const float4*>(&As[k][ty * 8]);
            float4 a1 = *reinterpret_cast<const float4*>(&As[k][ty * 8 + 4]);
            float4 b0 = *reinterpret_cast<const float4*>(&Bs[k][tx * 8]);
            float4 b1 = *reinterpret_cast<const float4*>(&Bs[k][tx * 8 + 4]);
            a[0]=a0.x; a[1]=a0.y; a[2]=a0.z; a[3]=a0.w;
            a[4]=a1.x; a[5]=a1.y; a[6]=a1.z; a[7]=a1.w;
            b[0]=b0.x; b[1]=b0.y; b[2]=b0.z; b[3]=b0.w;
            b[4]=b1.x; b[5]=b1.y; b[6]=b1.z; b[7]=b1.w;
            #pragma unroll
            for (int i = 0; i < 8; i++)
                #pragma unroll
                for (int j = 0; j < 8; j++)
                    acc[i][j] = fmaf(a[i], b[j], acc[i][j]);
        }
        __syncthreads();
    }

    #pragma unroll
    for (int i = 0; i < 8; i++) {
        const int r = row0 + ty * 8 + i;
        #pragma unroll
        for (int j = 0; j < 8; j++) {
            const int c = col0 + tx * 8 + j;
            if (c < N) {
                float v = acc[i][j];
                if (EPI == 1) v = softplusf(v + bias[c]);
                C[(size_t)r * ldc + c] = v;
            }
        }
    }
}

// ---------------------------------------------------------------------------
// Causal depthwise conv (k=4) + bias + silu : g_xz[:, :DI] -> g_u
// ---------------------------------------------------------------------------
__global__ void conv_silu_kernel(const float* __restrict__ conv_w,
                                 const float* __restrict__ conv_b)
{
    int idx = blockIdx.x * blockDim.x + threadIdx.x;   // over MR*DI
    if (idx >= MR * DI) return;
    int d = idx & (DI - 1);
    int row = idx >> 11;            // DI = 2048 = 2^11
    int l = row & (LL - 1);
    int b = row >> 10;              // LL = 1024 = 2^10

    float acc = conv_b[d];
    #pragma unroll
    for (int j = 0; j < DC; j++) {
        int ll = l - (DC - 1) + j;
        if (ll >= 0) {
            acc = fmaf(g_xz[(size_t)(b * LL + ll) * NXZ + d], conv_w[d * DC + j], acc);
        }
    }
    g_u[idx] = siluf(acc);
}

// ---------------------------------------------------------------------------
// Selective scan: one thread per (b, d, n). 16 lanes share (b,d).
// h_{l} = exp(dt*A[d,n]) * h_{l-1} + dt * B[b,l,n] * u[b,l,d]
// y[b,l,d] = sum_n h * C[b,l,n]
// ---------------------------------------------------------------------------
__global__ void scan_kernel(const float* __restrict__ A_log)
{
    int tid = blockIdx.x * blockDim.x + threadIdx.x;   // 0 .. BB*DI*DS-1
    int n  = tid & (DS - 1);
    int bd = tid >> 4;
    int d  = bd & (DI - 1);
    int b  = bd >> 11;

    const float An = -__expf(A_log[d * DS + n]);

    const float* dt_p = g_dt + (size_t)b * LL * DI + d;
    const float* u_p  = g_u  + (size_t)b * LL * DI + d;
    const float* bc_p = g_ssm + (size_t)b * LL * NSSM;
    float* y_p = g_y + (size_t)b * LL * DI + d;

    float h = 0.0f;
    for (int l = 0; l < LL; l++) {
        float dt_v = dt_p[(size_t)l * DI];
        float u_v  = u_p [(size_t)l * DI];
        float Bv   = bc_p[(size_t)l * NSSM + n];
        float Cv   = bc_p[(size_t)l * NSSM + DS + n];
        h = fmaf(__expf(dt_v * An), h, dt_v * Bv * u_v);
        float p = h * Cv;
        p += __shfl_xor_sync(0xffffffffu, p, 8);
        p += __shfl_xor_sync(0xffffffffu, p, 4);
        p += __shfl_xor_sync(0xffffffffu, p, 2);
        p += __shfl_xor_sync(0xffffffffu, p, 1);
        if (n == 0) y_p[(size_t)l * DI] = p;
    }
}

// ---------------------------------------------------------------------------
// Gate: y = (y + D[d]*u) * silu(z)   (in-place on g_y)
// ---------------------------------------------------------------------------
__global__ void gate_kernel(const float* __restrict__ Dvec)
{
    int idx = blockIdx.x * blockDim.x + threadIdx.x;   // over MR*DI
    if (idx >= MR * DI) return;
    int d = idx & (DI - 1);
    int row = idx >> 11;
    float z = g_xz[(size_t)row * NXZ + DI + d];
    float v = fmaf(Dvec[d], g_u[idx], g_y[idx]);
    g_y[idx] = v * siluf(z);
}

// ---------------------------------------------------------------------------
extern "C" void kernel_launch(void* const* d_in, const int* in_sizes, int n_in,
                              void* d_out, int out_size)
{
    const float* x         = (const float*)d_in[0];
    const float* in_proj_w = (const float*)d_in[1];
    const float* conv_w    = (const float*)d_in[2];
    const float* conv_b    = (const float*)d_in[3];
    const float* x_proj_w  = (const float*)d_in[4];
    const float* dt_proj_w = (const float*)d_in[5];
    const float* dt_proj_b = (const float*)d_in[6];
    const float* A_log     = (const float*)d_in[7];
    const float* Dvec      = (const float*)d_in[8];
    const float* out_proj_w= (const float*)d_in[9];
    float* out = (float*)d_out;

    float* xz;  cudaGetSymbolAddress((void**)&xz,  g_xz);
    float* u;   cudaGetSymbolAddress((void**)&u,   g_u);
    float* ssm; cudaGetSymbolAddress((void**)&ssm, g_ssm);
    float* dt;  cudaGetSymbolAddress((void**)&dt,  g_dt);
    float* y;   cudaGetSymbolAddress((void**)&y,   g_y);

    dim3 blk(256);

    // 1) xz = x @ in_proj_w          [2048,1024] @ [1024,4096]
    {
        dim3 grid(NXZ / GBN, MR / GBM);
        sgemm_kernel<0><<<grid, blk>>>(x, DM, in_proj_w, NXZ, xz, NXZ,
                                       MR, NXZ, DM, nullptr);
    }
    // 2) u = silu(causal_conv(x_inner) + b)
    conv_silu_kernel<<<(MR * DI + 255) / 256, blk>>>(conv_w, conv_b);

    // 3) ssm = u @ x_proj_w          [2048,2048] @ [2048,2080]
    {
        dim3 grid((NSSM + GBN - 1) / GBN, MR / GBM);
        sgemm_kernel<0><<<grid, blk>>>(u, DI, x_proj_w, NSSM, ssm, NSSM,
                                       MR, NSSM, DI, nullptr);
    }
    // 4) dt = softplus(ssm[:,32:] @ dt_proj_w + dt_proj_b)
    {
        dim3 grid(DI / GBN, MR / GBM);
        sgemm_kernel<1><<<grid, blk>>>(ssm + 2 * DS, NSSM, dt_proj_w, DI, dt, DI,
                                       MR, DI, DI, dt_proj_b);
    }
    // 5) selective scan -> y
    scan_kernel<<<(BB * DI * DS) / 256, blk>>>(A_log);

    // 6) gate: y = (y + D*u) * silu(z)
    gate_kernel<<<(MR * DI + 255) / 256, blk>>>(Dvec);

    // 7) out = y @ out_proj_w        [2048,2048] @ [2048,1024]
    {
        dim3 grid(DM / GBN, MR / GBM);
        sgemm_kernel<0><<<grid, blk>>>(y, DI, out_proj_w, DM, out, DM,
                                       MR, DM, DI, nullptr);
    }
}

// round 3
// speedup vs baseline: 1.8393x; 1.8393x over previous
#include <cuda_runtime.h>
#include <cuda_bf16.h>
#include <math.h>
#include <cstdint>

// Problem dims (fixed per reference)
#define BB 2
#define LL 1024
#define DM 1024
#define DS 16
#define DC 4
#define DI 2048
#define MR (BB*LL)          // 2048 rows
#define NXZ (2*DI)          // 4096
#define NSSM (2*DS+DI)      // 2080
#define NSSM_PAD 2176       // padded to multiple of 128

// tcgen05 only exists on arch-accelerated / family-specific targets.
#if defined(__CUDA_ARCH__) && (defined(__CUDA_ARCH_FEAT_SM103_ALL) || defined(__CUDA_ARCH_FEAT_SM100_ALL) || defined(__CUDA_ARCH_FAMILY_SPECIFIC__) || defined(__CUDA_ARCH_SPECIFIC__))
#define TC_OK 1
#else
#define TC_OK 0
#endif

// ---------------------------------------------------------------------------
// Scratch (device globals; allocation inside kernel_launch is forbidden)
// ---------------------------------------------------------------------------
__device__ __align__(16) float g_xz [MR*NXZ];    // [x_inner | z]
__device__ __align__(16) float g_u  [MR*DI];     // silu(conv(x_inner))
__device__ __align__(16) float g_ssm[MR*NSSM];   // [B(16) | C(16) | dt_in(2048)]
__device__ __align__(16) float g_dt [MR*DI];     // softplus(dt_in @ Wdt + b)
__device__ __align__(16) float g_y  [MR*DI];     // scan output, then gated

// bf16-split operand buffers (A: [M,K] row-major, B: [Npad,K] row-major = W^T)
__device__ __align__(256) __nv_bfloat16 g_ah[MR*DI];
__device__ __align__(256) __nv_bfloat16 g_al[MR*DI];
__device__ __align__(256) __nv_bfloat16 g_bh[NSSM_PAD*DI];
__device__ __align__(256) __nv_bfloat16 g_bl[NSSM_PAD*DI];

__device__ __forceinline__ float siluf(float x) {
    return x / (1.0f + __expf(-x));
}
__device__ __forceinline__ float softplusf(float x) {
    return fmaxf(x, 0.0f) + log1pf(__expf(-fabsf(x)));
}

// ---------------------------------------------------------------------------
// PTX helpers
// ---------------------------------------------------------------------------
__device__ __forceinline__ uint32_t smem_u32(const void* p) {
    uint32_t a;
    asm("{ .reg .u64 t; cvta.to.shared.u64 t, %1; cvt.u32.u64 %0, t; }" : "=r"(a) : "l"(p));
    return a;
}
#define SW(o) ((uint32_t)(o) ^ (((uint32_t)(o) >> 3) & 0x70u))

__device__ __forceinline__ uint32_t lds32(uint32_t a) {
    uint32_t v;
    asm volatile("ld.shared.b32 %0, [%1];" : "=r"(v) : "r"(a));
    return v;
}

#define TILE_B 16384                 // one 128x64-bf16 tile, SW128
#define BUF_B  (4*TILE_B)            // Ah,Al,Bh,Bl
#define SMEM_TOTAL (1024 + 2*BUF_B)  // 132096 bytes

// cp.async chunk loader: 4 tiles of 128 rows x 64 bf16 into SW128-swizzled smem
__device__ __forceinline__ void issue_chunk(
    uint32_t bufb,
    const __nv_bfloat16* __restrict__ Ah, const __nv_bfloat16* __restrict__ Al,
    const __nv_bfloat16* __restrict__ Bh, const __nv_bfloat16* __restrict__ Bl,
    int row0, int col0, int K, int k0, int tid)
{
    #pragma unroll
    for (int t = 0; t < 4; t++) {
        const __nv_bfloat16* src = (t == 0) ? Ah : (t == 1) ? Al : (t == 2) ? Bh : Bl;
        const int rbase = (t < 2) ? row0 : col0;
        #pragma unroll
        for (int i = 0; i < 4; i++) {
            const int u = tid + i * 256;          // 0..1023 : 16B units
            const int r = u >> 3;
            const int kc = (u & 7) * 8;
            const void* g = src + (size_t)(rbase + r) * K + (k0 + kc);
            uint32_t off = (uint32_t)(r * 128 + (u & 7) * 16);
            uint32_t dst = bufb + t * TILE_B + SW(off);
            asm volatile("cp.async.cg.shared.global [%0], [%1], 16;"
                         :: "r"(dst), "l"(g) : "memory");
        }
    }
    asm volatile("cp.async.commit_group;" ::: "memory");
}
template<int NW>
__device__ __forceinline__ void cpasync_wait() {
    asm volatile("cp.async.wait_group %0;" :: "n"(NW) : "memory");
}

#if TC_OK
// ----- tcgen05 machinery (sm_103a only) ------------------------------------
__device__ __forceinline__ uint32_t elect_one() {
    uint32_t pred;
    asm volatile("{\n\t.reg .pred p;\n\telect.sync _|p, 0xFFFFFFFF;\n\tselp.b32 %0, 1, 0, p;\n\t}" : "=r"(pred));
    return pred;
}
#define MBAR_INIT(addr, cnt) \
    asm volatile("mbarrier.init.shared.b64 [%0], %1;" :: "r"(addr), "r"(cnt) : "memory")
#define MBAR_INVAL(addr) \
    asm volatile("mbarrier.inval.shared.b64 [%0];" :: "r"(addr) : "memory")
#define MBAR_WAIT(addr, parity) do { \
    uint32_t _m = (addr); uint32_t _p = (parity); uint32_t _done; \
    asm volatile("{\n\t.reg .pred p;\n\tmbarrier.try_wait.parity.acquire.cta.shared::cta.b64 p, [%1], %2;\n\tselp.b32 %0, 1, 0, p;\n\t}" \
        : "=r"(_done) : "r"(_m), "r"(_p) : "memory"); \
    if (!_done) { \
        asm volatile("{\n\t.reg .pred P1;\n\tWL_%=:\n\tmbarrier.try_wait.parity.acquire.cta.shared::cta.b64 P1, [%0], %1, 0x989680;\n\t@P1 bra.uni WD_%=;\n\tbra.uni WL_%=;\n\tWD_%=:\n\t}" \
            :: "r"(_m), "r"(_p) : "memory"); \
    } } while (0)

#define TC_ALLOC(smem_addr, ncols) \
    asm volatile("tcgen05.alloc.cta_group::1.sync.aligned.shared::cta.b32 [%0], %1;" :: "r"(smem_addr), "r"(ncols) : "memory")
#define TC_DEALLOC(tmem_addr, ncols) \
    asm volatile("tcgen05.dealloc.cta_group::1.sync.aligned.b32 %0, %1;" :: "r"(tmem_addr), "r"(ncols))
#define TC_RELINQ() \
    asm volatile("tcgen05.relinquish_alloc_permit.cta_group::1.sync.aligned;")
#define TC_COMMIT(mbar) \
    asm volatile("tcgen05.commit.cta_group::1.mbarrier::arrive::one.shared::cluster.b64 [%0];" :: "r"(mbar) : "memory")
#define TC_FENCE_AFTER() asm volatile("tcgen05.fence::after_thread_sync;" ::: "memory")
#define TC_FENCE_BEFORE() asm volatile("tcgen05.fence::before_thread_sync;" ::: "memory")
#define TC_WAIT_LD() asm volatile("tcgen05.wait::ld.sync.aligned;" ::: "memory")

#define TC_LD_X32(r, addr) \
    asm volatile("tcgen05.ld.sync.aligned.32x32b.x32.b32 " \
        "{%0, %1, %2, %3, %4, %5, %6, %7, %8, %9, %10, %11, %12, %13, %14, %15, " \
        "%16, %17, %18, %19, %20, %21, %22, %23, %24, %25, %26, %27, %28, %29, %30, %31}, [%32];" \
        : "=r"((r)[0]),  "=r"((r)[1]),  "=r"((r)[2]),  "=r"((r)[3]), \
          "=r"((r)[4]),  "=r"((r)[5]),  "=r"((r)[6]),  "=r"((r)[7]), \
          "=r"((r)[8]),  "=r"((r)[9]),  "=r"((r)[10]), "=r"((r)[11]), \
          "=r"((r)[12]), "=r"((r)[13]), "=r"((r)[14]), "=r"((r)[15]), \
          "=r"((r)[16]), "=r"((r)[17]), "=r"((r)[18]), "=r"((r)[19]), \
          "=r"((r)[20]), "=r"((r)[21]), "=r"((r)[22]), "=r"((r)[23]), \
          "=r"((r)[24]), "=r"((r)[25]), "=r"((r)[26]), "=r"((r)[27]), \
          "=r"((r)[28]), "=r"((r)[29]), "=r"((r)[30]), "=r"((r)[31]) \
        : "r"(addr))

// SW128 SMEM descriptor (layout=2, version=1, SBO=64, LBO=1)
static constexpr uint64_t DESC_BASE_SW128 =
    (uint64_t(2) << 61) | (uint64_t(1) << 46) | (uint64_t(64) << 32) | (uint64_t(1) << 16);
__device__ __forceinline__ uint64_t mk_desc(uint32_t addr) {
    return DESC_BASE_SW128 | ((uint64_t)(addr >> 4) & 0x3FFF);
}
__device__ __forceinline__ void mma_f16_ss(uint32_t d, uint64_t a, uint64_t b,
                                           uint32_t idesc, bool en) {
    uint32_t e = en ? 1u : 0u;
    asm volatile(
        "{\n\t.reg .pred p;\n\tsetp.ne.u32 p, %5, 0;\n\t"
        "tcgen05.mma.cta_group::1.kind::f16 [%0], %1, %2, %3, {%4, %4, %4, %4}, p;\n\t}"
        :: "r"(d), "l"(a), "l"(b), "r"(idesc), "r"(0u), "r"(e) : "memory");
}
// dtype=F32, atype/btype=BF16, N=128, M=128  -> 0x8200490
static constexpr uint32_t IDESC_128x128 =
    (1u << 4) | (1u << 7) | (1u << 10) | ((128u / 8) << 17) | ((128u / 16) << 24);
#else
// ----- HMMA fallback machinery (valid on plain sm_103) ----------------------
__device__ __forceinline__ void mma_bf16(float* d, const uint32_t* a, const uint32_t* b) {
    asm volatile(
        "mma.sync.aligned.m16n8k16.row.col.f32.bf16.bf16.f32 "
        "{%0,%1,%2,%3}, {%4,%5,%6,%7}, {%8,%9}, {%0,%1,%2,%3};"
        : "+f"(d[0]), "+f"(d[1]), "+f"(d[2]), "+f"(d[3])
        : "r"(a[0]), "r"(a[1]), "r"(a[2]), "r"(a[3]), "r"(b[0]), "r"(b[1]));
}
#endif

// ---------------------------------------------------------------------------
// GEMM: C[M,N] = (Ah+Al)[M,K] @ (Bh+Bl)[Npad,K]^T   (3-term bf16 split)
// 128x128 tile / CTA, K chunks of 64 bf16, cp.async double-buffered.
// EPI==1: softplus(C + bias[col]);  GUARD==1: guard stores col < N.
// ---------------------------------------------------------------------------
template<int EPI, int GUARD>
__global__ __launch_bounds__(256, 1)
void gemm_tc(const __nv_bfloat16* __restrict__ Ah, const __nv_bfloat16* __restrict__ Al,
             const __nv_bfloat16* __restrict__ Bh, const __nv_bfloat16* __restrict__ Bl,
             float* __restrict__ C, int ldc, int N, int K,
             const float* __restrict__ bias)
{
    extern __shared__ char smem[];
    const uint32_t sbase = smem_u32(smem);
    const int tid = threadIdx.x;
    const int wid = tid >> 5;
    const int lane = tid & 31;
    const int row0 = blockIdx.y * 128;
    const int col0 = blockIdx.x * 128;
    const int nc = K >> 6;   // #chunks of 64 (16 or 32 here; always even)

#if TC_OK
    if (wid == 0) {
        TC_ALLOC(sbase, 128);
        TC_RELINQ();
    }
    if (tid == 0) {
        MBAR_INIT(sbase + 8, 1);
        MBAR_INIT(sbase + 16, 1);
    }
    __syncthreads();
    uint32_t tmem;
    asm volatile("ld.shared.b32 %0, [%1];" : "=r"(tmem) : "r"(sbase));

    issue_chunk(sbase + 1024,         Ah, Al, Bh, Bl, row0, col0, K, 0,  tid);
    issue_chunk(sbase + 1024 + BUF_B, Ah, Al, Bh, Bl, row0, col0, K, 64, tid);

    int ph0 = 0, ph1 = 0;
    for (int c = 0; c < nc; c++) {
        const int buf = c & 1;
        const uint32_t bufb = sbase + 1024 + buf * BUF_B;
        if (c + 1 < nc) cpasync_wait<1>(); else cpasync_wait<0>();
        asm volatile("fence.proxy.async.shared::cta;" ::: "memory");
        __syncthreads();

        if (wid == 0 && elect_one()) {
            uint64_t dAh = mk_desc(bufb + 0 * TILE_B);
            uint64_t dAl = mk_desc(bufb + 1 * TILE_B);
            uint64_t dBh = mk_desc(bufb + 2 * TILE_B);
            uint64_t dBl = mk_desc(bufb + 3 * TILE_B);
            #pragma unroll
            for (int ks = 0; ks < 4; ks++) {
                const uint64_t o = (uint64_t)(ks * 2);   // 16 bf16 = 32B = 2 units
                mma_f16_ss(tmem, dAh + o, dBh + o, IDESC_128x128, !(c == 0 && ks == 0));
                mma_f16_ss(tmem, dAh + o, dBl + o, IDESC_128x128, true);
                mma_f16_ss(tmem, dAl + o, dBh + o, IDESC_128x128, true);
            }
            TC_COMMIT(sbase + 8 + buf * 8);
        }
        if (c + 2 < nc) {
            // buffer reuse: wait for this chunk's MMAs to finish reading it
            if (buf == 0) { MBAR_WAIT(sbase + 8,  ph0); ph0 ^= 1; }
            else          { MBAR_WAIT(sbase + 16, ph1); ph1 ^= 1; }
            issue_chunk(bufb, Ah, Al, Bh, Bl, row0, col0, K, (c + 2) << 6, tid);
        }
    }
    // drain last two chunk commits (nc even: nc-2 -> buf0, nc-1 -> buf1)
    MBAR_WAIT(sbase + 8,  ph0);
    MBAR_WAIT(sbase + 16, ph1);
    TC_FENCE_AFTER();

    if (wid < 4) {
        const int r = row0 + wid * 32 + lane;
        #pragma unroll
        for (int nb = 0; nb < 4; nb++) {
            uint32_t regs[32];
            TC_LD_X32(regs, tmem + nb * 32);
            TC_WAIT_LD();
            const int cb = col0 + nb * 32;
            if (EPI == 0 && GUARD == 0) {
                float4* dst = reinterpret_cast<float4*>(C + (size_t)r * ldc + cb);
                #pragma unroll
                for (int j = 0; j < 8; j++) {
                    float4 v;
                    v.x = __uint_as_float(regs[4 * j + 0]);
                    v.y = __uint_as_float(regs[4 * j + 1]);
                    v.z = __uint_as_float(regs[4 * j + 2]);
                    v.w = __uint_as_float(regs[4 * j + 3]);
                    dst[j] = v;
                }
            } else {
                #pragma unroll
                for (int j = 0; j < 32; j++) {
                    const int cc = cb + j;
                    if (!GUARD || cc < N) {
                        float v = __uint_as_float(regs[j]);
                        if (EPI) v = softplusf(v + bias[cc]);
                        C[(size_t)r * ldc + cc] = v;
                    }
                }
            }
        }
        TC_FENCE_BEFORE();
    }
    __syncthreads();
    if (tid == 0) { MBAR_INVAL(sbase + 8); MBAR_INVAL(sbase + 16); }
    __syncthreads();
    if (wid == 0) {
        TC_DEALLOC(tmem, 128);
    }
#else
    // ------------------ HMMA fallback (mma.sync m16n8k16 bf16) -------------
    const int wm = wid & 3;          // 4 warps along M (32 rows each)
    const int wn = wid >> 2;         // 2 warps along N (64 cols each)
    const int g  = lane >> 2;        // 0..7
    const int t2 = (lane & 3) * 2;   // 0,2,4,6

    float acc[2][8][4];
    #pragma unroll
    for (int mt = 0; mt < 2; mt++)
        #pragma unroll
        for (int nt = 0; nt < 8; nt++)
            #pragma unroll
            for (int j = 0; j < 4; j++) acc[mt][nt][j] = 0.0f;

    issue_chunk(sbase + 1024,         Ah, Al, Bh, Bl, row0, col0, K, 0,  tid);
    issue_chunk(sbase + 1024 + BUF_B, Ah, Al, Bh, Bl, row0, col0, K, 64, tid);

    for (int c = 0; c < nc; c++) {
        const uint32_t bufb = sbase + 1024 + (c & 1) * BUF_B;
        if (c + 1 < nc) cpasync_wait<1>(); else cpasync_wait<0>();
        __syncthreads();

        const uint32_t aH_t = bufb + 0 * TILE_B, aL_t = bufb + 1 * TILE_B;
        const uint32_t bH_t = bufb + 2 * TILE_B, bL_t = bufb + 3 * TILE_B;

        #pragma unroll
        for (int ks = 0; ks < 4; ks++) {
            const int kb = ks * 32 + t2 * 2;     // byte col of low k-pair
            uint32_t aH[2][4], aL[2][4], bH[8][2], bL[8][2];
            #pragma unroll
            for (int mt = 0; mt < 2; mt++) {
                const int r0 = (wm * 32 + mt * 16 + g) * 128;
                const int r1 = r0 + 8 * 128;
                aH[mt][0] = lds32(aH_t + SW(r0 + kb));
                aH[mt][1] = lds32(aH_t + SW(r1 + kb));
                aH[mt][2] = lds32(aH_t + SW(r0 + kb + 16));
                aH[mt][3] = lds32(aH_t + SW(r1 + kb + 16));
            }
            #pragma unroll
            for (int nt = 0; nt < 8; nt++) {
                const int rn = (wn * 64 + nt * 8 + g) * 128;
                bH[nt][0] = lds32(bH_t + SW(rn + kb));
                bH[nt][1] = lds32(bH_t + SW(rn + kb + 16));
            }
            #pragma unroll
            for (int mt = 0; mt < 2; mt++)
                #pragma unroll
                for (int nt = 0; nt < 8; nt++)
                    mma_bf16(acc[mt][nt], aH[mt], bH[nt]);
            #pragma unroll
            for (int nt = 0; nt < 8; nt++) {
                const int rn = (wn * 64 + nt * 8 + g) * 128;
                bL[nt][0] = lds32(bL_t + SW(rn + kb));
                bL[nt][1] = lds32(bL_t + SW(rn + kb + 16));
            }
            #pragma unroll
            for (int mt = 0; mt < 2; mt++)
                #pragma unroll
                for (int nt = 0; nt < 8; nt++)
                    mma_bf16(acc[mt][nt], aH[mt], bL[nt]);
            #pragma unroll
            for (int mt = 0; mt < 2; mt++) {
                const int r0 = (wm * 32 + mt * 16 + g) * 128;
                const int r1 = r0 + 8 * 128;
                aL[mt][0] = lds32(aL_t + SW(r0 + kb));
                aL[mt][1] = lds32(aL_t + SW(r1 + kb));
                aL[mt][2] = lds32(aL_t + SW(r0 + kb + 16));
                aL[mt][3] = lds32(aL_t + SW(r1 + kb + 16));
            }
            #pragma unroll
            for (int mt = 0; mt < 2; mt++)
                #pragma unroll
                for (int nt = 0; nt < 8; nt++)
                    mma_bf16(acc[mt][nt], aL[mt], bH[nt]);
        }
        __syncthreads();
        if (c + 2 < nc)
            issue_chunk(bufb, Ah, Al, Bh, Bl, row0, col0, K, (c + 2) << 6, tid);
    }

    // epilogue
    #pragma unroll
    for (int mt = 0; mt < 2; mt++) {
        const int r0 = row0 + wm * 32 + mt * 16 + g;
        const int r1 = r0 + 8;
        #pragma unroll
        for (int nt = 0; nt < 8; nt++) {
            const int c0 = col0 + wn * 64 + nt * 8 + t2;
            float v0 = acc[mt][nt][0], v1 = acc[mt][nt][1];
            float v2 = acc[mt][nt][2], v3 = acc[mt][nt][3];
            if (EPI) {
                v0 = softplusf(v0 + bias[c0]);
                v1 = softplusf(v1 + bias[c0 + 1]);
                v2 = softplusf(v2 + bias[c0]);
                v3 = softplusf(v3 + bias[c0 + 1]);
            }
            if (!GUARD || c0 + 1 < N) {
                *reinterpret_cast<float2*>(C + (size_t)r0 * ldc + c0) = make_float2(v0, v1);
                *reinterpret_cast<float2*>(C + (size_t)r1 * ldc + c0) = make_float2(v2, v3);
            } else {
                if (c0 < N) { C[(size_t)r0 * ldc + c0] = v0; C[(size_t)r1 * ldc + c0] = v2; }
            }
        }
    }
#endif
}

// ---------------------------------------------------------------------------
// fp32 -> bf16 hi/lo split for activations: src [M,K] with row stride lda
// ---------------------------------------------------------------------------
__global__ void split_a_kernel(const float* __restrict__ src, int lda, int kshift,
                               __nv_bfloat16* __restrict__ hi,
                               __nv_bfloat16* __restrict__ lo, int total)
{
    int idx = blockIdx.x * blockDim.x + threadIdx.x;
    if (idx >= total) return;
    int K = 1 << kshift;
    int r = idx >> kshift;
    int c = idx & (K - 1);
    float v = src[(size_t)r * lda + c];
    __nv_bfloat16 h = __float2bfloat16(v);
    hi[idx] = h;
    lo[idx] = __float2bfloat16(v - __bfloat162float(h));
}

// ---------------------------------------------------------------------------
// W [K,N] row-major -> W^T [Npad,K] bf16 hi/lo (zero-padded rows N..Npad)
// ---------------------------------------------------------------------------
__global__ void split_w_kernel(const float* __restrict__ W, int K, int N, int Npad,
                               __nv_bfloat16* __restrict__ hi,
                               __nv_bfloat16* __restrict__ lo)
{
    __shared__ float t[32][33];
    const int n0 = blockIdx.x * 32, k0 = blockIdx.y * 32;
    const int tx = threadIdx.x, ty = threadIdx.y;
    const int n = n0 + tx, k = k0 + ty;
    t[ty][tx] = (n < N) ? W[(size_t)k * N + n] : 0.0f;
    __syncthreads();
    const int on = n0 + ty, ok = k0 + tx;
    float v = t[tx][ty];
    __nv_bfloat16 h = __float2bfloat16(v);
    hi[(size_t)on * K + ok] = h;
    lo[(size_t)on * K + ok] = __float2bfloat16(v - __bfloat162float(h));
}

// ---------------------------------------------------------------------------
// Causal depthwise conv (k=4) + bias + silu : g_xz[:, :DI] -> g_u
// ---------------------------------------------------------------------------
__global__ void conv_silu_kernel(const float* __restrict__ conv_w,
                                 const float* __restrict__ conv_b)
{
    int idx = blockIdx.x * blockDim.x + threadIdx.x;
    if (idx >= MR * DI) return;
    int d = idx & (DI - 1);
    int row = idx >> 11;
    int l = row & (LL - 1);
    int b = row >> 10;

    float acc = conv_b[d];
    #pragma unroll
    for (int j = 0; j < DC; j++) {
        int ll = l - (DC - 1) + j;
        if (ll >= 0) {
            acc = fmaf(g_xz[(size_t)(b * LL + ll) * NXZ + d], conv_w[d * DC + j], acc);
        }
    }
    g_u[idx] = siluf(acc);
}

// ---------------------------------------------------------------------------
// Selective scan: one thread per (b, d, n); 16 lanes share (b,d)
// ---------------------------------------------------------------------------
__global__ void scan_kernel(const float* __restrict__ A_log)
{
    int tid = blockIdx.x * blockDim.x + threadIdx.x;
    int n  = tid & (DS - 1);
    int bd = tid >> 4;
    int d  = bd & (DI - 1);
    int b  = bd >> 11;

    const float An = -__expf(A_log[d * DS + n]);

    const float* dt_p = g_dt + (size_t)b * LL * DI + d;
    const float* u_p  = g_u  + (size_t)b * LL * DI + d;
    const float* bc_p = g_ssm + (size_t)b * LL * NSSM;
    float* y_p = g_y + (size_t)b * LL * DI + d;

    float h = 0.0f;
    for (int l = 0; l < LL; l++) {
        float dt_v = dt_p[(size_t)l * DI];
        float u_v  = u_p [(size_t)l * DI];
        float Bv   = bc_p[(size_t)l * NSSM + n];
        float Cv   = bc_p[(size_t)l * NSSM + DS + n];
        h = fmaf(__expf(dt_v * An), h, dt_v * Bv * u_v);
        float p = h * Cv;
        p += __shfl_xor_sync(0xffffffffu, p, 8);
        p += __shfl_xor_sync(0xffffffffu, p, 4);
        p += __shfl_xor_sync(0xffffffffu, p, 2);
        p += __shfl_xor_sync(0xffffffffu, p, 1);
        if (n == 0) y_p[(size_t)l * DI] = p;
    }
}

// ---------------------------------------------------------------------------
// Gate: y = (y + D[d]*u) * silu(z)
// ---------------------------------------------------------------------------
__global__ void gate_kernel(const float* __restrict__ Dvec)
{
    int idx = blockIdx.x * blockDim.x + threadIdx.x;
    if (idx >= MR * DI) return;
    int d = idx & (DI - 1);
    int row = idx >> 11;
    float z = g_xz[(size_t)row * NXZ + DI + d];
    float v = fmaf(Dvec[d], g_u[idx], g_y[idx]);
    g_y[idx] = v * siluf(z);
}

// ---------------------------------------------------------------------------
extern "C" void kernel_launch(void* const* d_in, const int* in_sizes, int n_in,
                              void* d_out, int out_size)
{
    const float* x         = (const float*)d_in[0];
    const float* in_proj_w = (const float*)d_in[1];
    const float* conv_w    = (const float*)d_in[2];
    const float* conv_b    = (const float*)d_in[3];
    const float* x_proj_w  = (const float*)d_in[4];
    const float* dt_proj_w = (const float*)d_in[5];
    const float* dt_proj_b = (const float*)d_in[6];
    const float* A_log     = (const float*)d_in[7];
    const float* Dvec      = (const float*)d_in[8];
    const float* out_proj_w= (const float*)d_in[9];
    float* out = (float*)d_out;

    float* xz;  cudaGetSymbolAddress((void**)&xz,  g_xz);
    float* u;   cudaGetSymbolAddress((void**)&u,   g_u);
    float* ssm; cudaGetSymbolAddress((void**)&ssm, g_ssm);
    float* dt;  cudaGetSymbolAddress((void**)&dt,  g_dt);
    float* y;   cudaGetSymbolAddress((void**)&y,   g_y);
    __nv_bfloat16 *ah, *al, *bh, *bl;
    cudaGetSymbolAddress((void**)&ah, g_ah);
    cudaGetSymbolAddress((void**)&al, g_al);
    cudaGetSymbolAddress((void**)&bh, g_bh);
    cudaGetSymbolAddress((void**)&bl, g_bl);

    cudaFuncSetAttribute(gemm_tc<0,0>, cudaFuncAttributeMaxDynamicSharedMemorySize, SMEM_TOTAL);
    cudaFuncSetAttribute(gemm_tc<0,1>, cudaFuncAttributeMaxDynamicSharedMemorySize, SMEM_TOTAL);
    cudaFuncSetAttribute(gemm_tc<1,0>, cudaFuncAttributeMaxDynamicSharedMemorySize, SMEM_TOTAL);

    dim3 blk(256);
    dim3 tblk(32, 32);

    // ---- GEMM1: xz = x @ in_proj_w   [2048,1024]@[1024,4096] ----
    split_a_kernel<<<(MR * DM + 255) / 256, blk>>>(x, DM, 10, ah, al, MR * DM);
    split_w_kernel<<<dim3(NXZ / 32, DM / 32), tblk>>>(in_proj_w, DM, NXZ, NXZ, bh, bl);
    gemm_tc<0,0><<<dim3(NXZ / 128, MR / 128), blk, SMEM_TOTAL>>>(
        ah, al, bh, bl, xz, NXZ, NXZ, DM, nullptr);

    // ---- conv + silu -> u ----
    conv_silu_kernel<<<(MR * DI + 255) / 256, blk>>>(conv_w, conv_b);

    // ---- GEMM2: ssm = u @ x_proj_w   [2048,2048]@[2048,2080] ----
    split_a_kernel<<<(MR * DI + 255) / 256, blk>>>(u, DI, 11, ah, al, MR * DI);
    split_w_kernel<<<dim3(NSSM_PAD / 32, DI / 32), tblk>>>(x_proj_w, DI, NSSM, NSSM_PAD, bh, bl);
    gemm_tc<0,1><<<dim3(NSSM_PAD / 128, MR / 128), blk, SMEM_TOTAL>>>(
        ah, al, bh, bl, ssm, NSSM, NSSM, DI, nullptr);

    // ---- GEMM3: dt = softplus(ssm[:,32:] @ dt_proj_w + b) ----
    split_a_kernel<<<(MR * DI + 255) / 256, blk>>>(ssm + 2 * DS, NSSM, 11, ah, al, MR * DI);
    split_w_kernel<<<dim3(DI / 32, DI / 32), tblk>>>(dt_proj_w, DI, DI, DI, bh, bl);
    gemm_tc<1,0><<<dim3(DI / 128, MR / 128), blk, SMEM_TOTAL>>>(
        ah, al, bh, bl, dt, DI, DI, DI, dt_proj_b);

    // ---- selective scan -> y ----
    scan_kernel<<<(BB * DI * DS) / 256, blk>>>(A_log);

    // ---- gate ----
    gate_kernel<<<(MR * DI + 255) / 256, blk>>>(Dvec);

    // ---- GEMM4: out = y @ out_proj_w  [2048,2048]@[2048,1024] ----
    split_a_kernel<<<(MR * DI + 255) / 256, blk>>>(y, DI, 11, ah, al, MR * DI);
    split_w_kernel<<<dim3(DM / 32, DI / 32), tblk>>>(out_proj_w, DI, DM, DM, bh, bl);
    gemm_tc<0,0><<<dim3(DM / 128, MR / 128), blk, SMEM_TOTAL>>>(
        ah, al, bh, bl, out, DM, DM, DI, nullptr);
}

// round 5
// speedup vs baseline: 4.2744x; 2.3240x over previous
#include <cuda_runtime.h>
#include <cuda_bf16.h>
#include <math.h>
#include <cstdint>

// Problem dims (fixed per reference)
#define BB 2
#define LL 1024
#define DM 1024
#define DS 16
#define DC 4
#define DI 2048
#define MR (BB*LL)          // 2048 rows
#define NXZ (2*DI)          // 4096
#define NSSM (2*DS+DI)      // 2080
#define NSSM_PAD 2176       // padded to multiple of 128
#define NCH 16              // scan chunks
#define CHL 64              // steps per chunk (NCH*CHL == LL)

// tcgen05 only exists on arch-accelerated / family-specific targets.
#if defined(__CUDA_ARCH__) && (defined(__CUDA_ARCH_FEAT_SM103_ALL) || defined(__CUDA_ARCH_FEAT_SM100_ALL) || defined(__CUDA_ARCH_FAMILY_SPECIFIC__) || defined(__CUDA_ARCH_SPECIFIC__))
#define TC_OK 1
#else
#define TC_OK 0
#endif

// ---------------------------------------------------------------------------
// Scratch (device globals; allocation inside kernel_launch is forbidden)
// ---------------------------------------------------------------------------
__device__ __align__(16) float g_xz [MR*NXZ];    // [x_inner | z]
__device__ __align__(16) float g_u  [MR*DI];     // silu(conv(x_inner))
__device__ __align__(16) float g_ssm[MR*NSSM];   // only cols [0,32) used in fp32
__device__ __align__(16) float g_dt [MR*DI];     // softplus(dt_in @ Wdt + b)
__device__ __align__(16) float g_y  [MR*DI];     // scan output
__device__ __align__(16) float g_hfin[BB*DI*NCH*DS];  // chunk-local / prefix states
__device__ __align__(16) float g_P   [BB*DI*NCH*DS];  // chunk decay products

// bf16-split operand buffers (A: [M,K] row-major, B: [Npad,K] row-major = W^T)
__device__ __align__(256) __nv_bfloat16 g_ah[MR*DI];
__device__ __align__(256) __nv_bfloat16 g_al[MR*DI];
__device__ __align__(256) __nv_bfloat16 g_bh[NSSM_PAD*DI];
__device__ __align__(256) __nv_bfloat16 g_bl[NSSM_PAD*DI];
// dedicated buffers for dt_in split (GEMM2 output -> GEMM3 input); avoids the
// in-place race of writing GEMM2's own A-operand buffers from its epilogue.
__device__ __align__(256) __nv_bfloat16 g_ch[MR*DI];
__device__ __align__(256) __nv_bfloat16 g_cl[MR*DI];

__device__ __forceinline__ float siluf(float x) {
    return x / (1.0f + __expf(-x));
}
__device__ __forceinline__ float softplusf(float x) {
    return fmaxf(x, 0.0f) + log1pf(__expf(-fabsf(x)));
}

// ---------------------------------------------------------------------------
// PTX helpers
// ---------------------------------------------------------------------------
__device__ __forceinline__ uint32_t smem_u32(const void* p) {
    uint32_t a;
    asm("{ .reg .u64 t; cvta.to.shared.u64 t, %1; cvt.u32.u64 %0, t; }" : "=r"(a) : "l"(p));
    return a;
}
#define SW(o) ((uint32_t)(o) ^ (((uint32_t)(o) >> 3) & 0x70u))

__device__ __forceinline__ uint32_t lds32(uint32_t a) {
    uint32_t v;
    asm volatile("ld.shared.b32 %0, [%1];" : "=r"(v) : "r"(a));
    return v;
}

#define TILE_B 16384                 // one 128x64-bf16 tile, SW128
#define BUF_B  (4*TILE_B)            // Ah,Al,Bh,Bl
#define SMEM_TOTAL (1024 + 3*BUF_B)  // 197632 bytes (3-stage)

// cp.async chunk loader: 4 tiles of 128 rows x 64 bf16 into SW128-swizzled smem
__device__ __forceinline__ void issue_chunk(
    uint32_t bufb,
    const __nv_bfloat16* __restrict__ Ah, const __nv_bfloat16* __restrict__ Al,
    const __nv_bfloat16* __restrict__ Bh, const __nv_bfloat16* __restrict__ Bl,
    int row0, int col0, int K, int k0, int tid)
{
    #pragma unroll
    for (int t = 0; t < 4; t++) {
        const __nv_bfloat16* src = (t == 0) ? Ah : (t == 1) ? Al : (t == 2) ? Bh : Bl;
        const int rbase = (t < 2) ? row0 : col0;
        #pragma unroll
        for (int i = 0; i < 4; i++) {
            const int u = tid + i * 256;          // 0..1023 : 16B units
            const int r = u >> 3;
            const int kc = (u & 7) * 8;
            const void* g = src + (size_t)(rbase + r) * K + (k0 + kc);
            uint32_t off = (uint32_t)(r * 128 + (u & 7) * 16);
            uint32_t dst = bufb + t * TILE_B + SW(off);
            asm volatile("cp.async.cg.shared.global [%0], [%1], 16;"
                         :: "r"(dst), "l"(g) : "memory");
        }
    }
    asm volatile("cp.async.commit_group;" ::: "memory");
}
template<int NW>
__device__ __forceinline__ void cpasync_wait() {
    asm volatile("cp.async.wait_group %0;" :: "n"(NW) : "memory");
}

#if TC_OK
// ----- tcgen05 machinery (sm_103a only) ------------------------------------
__device__ __forceinline__ uint32_t elect_one() {
    uint32_t pred;
    asm volatile("{\n\t.reg .pred p;\n\telect.sync _|p, 0xFFFFFFFF;\n\tselp.b32 %0, 1, 0, p;\n\t}" : "=r"(pred));
    return pred;
}
#define MBAR_INIT(addr, cnt) \
    asm volatile("mbarrier.init.shared.b64 [%0], %1;" :: "r"(addr), "r"(cnt) : "memory")
#define MBAR_INVAL(addr) \
    asm volatile("mbarrier.inval.shared.b64 [%0];" :: "r"(addr) : "memory")
#define MBAR_WAIT(addr, parity) do { \
    uint32_t _m = (addr); uint32_t _p = (parity); uint32_t _done; \
    asm volatile("{\n\t.reg .pred p;\n\tmbarrier.try_wait.parity.acquire.cta.shared::cta.b64 p, [%1], %2;\n\tselp.b32 %0, 1, 0, p;\n\t}" \
        : "=r"(_done) : "r"(_m), "r"(_p) : "memory"); \
    if (!_done) { \
        asm volatile("{\n\t.reg .pred P1;\n\tWL_%=:\n\tmbarrier.try_wait.parity.acquire.cta.shared::cta.b64 P1, [%0], %1, 0x989680;\n\t@P1 bra.uni WD_%=;\n\tbra.uni WL_%=;\n\tWD_%=:\n\t}" \
            :: "r"(_m), "r"(_p) : "memory"); \
    } } while (0)

#define TC_ALLOC(smem_addr, ncols) \
    asm volatile("tcgen05.alloc.cta_group::1.sync.aligned.shared::cta.b32 [%0], %1;" :: "r"(smem_addr), "r"(ncols) : "memory")
#define TC_DEALLOC(tmem_addr, ncols) \
    asm volatile("tcgen05.dealloc.cta_group::1.sync.aligned.b32 %0, %1;" :: "r"(tmem_addr), "r"(ncols))
#define TC_RELINQ() \
    asm volatile("tcgen05.relinquish_alloc_permit.cta_group::1.sync.aligned;")
#define TC_COMMIT(mbar) \
    asm volatile("tcgen05.commit.cta_group::1.mbarrier::arrive::one.shared::cluster.b64 [%0];" :: "r"(mbar) : "memory")
#define TC_FENCE_AFTER() asm volatile("tcgen05.fence::after_thread_sync;" ::: "memory")
#define TC_FENCE_BEFORE() asm volatile("tcgen05.fence::before_thread_sync;" ::: "memory")
#define TC_WAIT_LD() asm volatile("tcgen05.wait::ld.sync.aligned;" ::: "memory")

#define TC_LD_X32(r, addr) \
    asm volatile("tcgen05.ld.sync.aligned.32x32b.x32.b32 " \
        "{%0, %1, %2, %3, %4, %5, %6, %7, %8, %9, %10, %11, %12, %13, %14, %15, " \
        "%16, %17, %18, %19, %20, %21, %22, %23, %24, %25, %26, %27, %28, %29, %30, %31}, [%32];" \
        : "=r"((r)[0]),  "=r"((r)[1]),  "=r"((r)[2]),  "=r"((r)[3]), \
          "=r"((r)[4]),  "=r"((r)[5]),  "=r"((r)[6]),  "=r"((r)[7]), \
          "=r"((r)[8]),  "=r"((r)[9]),  "=r"((r)[10]), "=r"((r)[11]), \
          "=r"((r)[12]), "=r"((r)[13]), "=r"((r)[14]), "=r"((r)[15]), \
          "=r"((r)[16]), "=r"((r)[17]), "=r"((r)[18]), "=r"((r)[19]), \
          "=r"((r)[20]), "=r"((r)[21]), "=r"((r)[22]), "=r"((r)[23]), \
          "=r"((r)[24]), "=r"((r)[25]), "=r"((r)[26]), "=r"((r)[27]), \
          "=r"((r)[28]), "=r"((r)[29]), "=r"((r)[30]), "=r"((r)[31]) \
        : "r"(addr))

// SW128 SMEM descriptor (layout=2, version=1, SBO=64, LBO=1)
static constexpr uint64_t DESC_BASE_SW128 =
    (uint64_t(2) << 61) | (uint64_t(1) << 46) | (uint64_t(64) << 32) | (uint64_t(1) << 16);
__device__ __forceinline__ uint64_t mk_desc(uint32_t addr) {
    return DESC_BASE_SW128 | ((uint64_t)(addr >> 4) & 0x3FFF);
}
__device__ __forceinline__ void mma_f16_ss(uint32_t d, uint64_t a, uint64_t b,
                                           uint32_t idesc, bool en) {
    uint32_t e = en ? 1u : 0u;
    asm volatile(
        "{\n\t.reg .pred p;\n\tsetp.ne.u32 p, %5, 0;\n\t"
        "tcgen05.mma.cta_group::1.kind::f16 [%0], %1, %2, %3, {%4, %4, %4, %4}, p;\n\t}"
        :: "r"(d), "l"(a), "l"(b), "r"(idesc), "r"(0u), "r"(e) : "memory");
}
static constexpr uint32_t IDESC_128x128 =
    (1u << 4) | (1u << 7) | (1u << 10) | ((128u / 8) << 17) | ((128u / 16) << 24);
#else
// ----- HMMA fallback machinery (valid on plain sm_103) ----------------------
__device__ __forceinline__ void mma_bf16(float* d, const uint32_t* a, const uint32_t* b) {
    asm volatile(
        "mma.sync.aligned.m16n8k16.row.col.f32.bf16.bf16.f32 "
        "{%0,%1,%2,%3}, {%4,%5,%6,%7}, {%8,%9}, {%0,%1,%2,%3};"
        : "+f"(d[0]), "+f"(d[1]), "+f"(d[2]), "+f"(d[3])
        : "r"(a[0]), "r"(a[1]), "r"(a[2]), "r"(a[3]), "r"(b[0]), "r"(b[1]));
}
#endif

// ---------------------------------------------------------------------------
// GEMM: C[M,N] = (Ah+Al)[M,K] @ (Bh+Bl)[Npad,K]^T   (3-term bf16 split)
// 128x128 tile / CTA, K chunks of 64 bf16, 3-stage cp.async pipeline.
// EPI==1: softplus(C + bias[col]).
// GUARD==1: guard stores col < N.
// WSPLIT==1: fp32 store only for col<32; cols>=32 written as bf16 hi/lo
//            at [row, col-32] into whi/wlo (row stride wld). whi/wlo MUST NOT
//            alias this GEMM's operands.
// ---------------------------------------------------------------------------
template<int EPI, int GUARD, int WSPLIT>
__global__ __launch_bounds__(256, 1)
void gemm_tc(const __nv_bfloat16* __restrict__ Ah, const __nv_bfloat16* __restrict__ Al,
             const __nv_bfloat16* __restrict__ Bh, const __nv_bfloat16* __restrict__ Bl,
             float* __restrict__ C, int ldc, int N, int K,
             const float* __restrict__ bias,
             __nv_bfloat16* __restrict__ whi, __nv_bfloat16* __restrict__ wlo, int wld)
{
    extern __shared__ char smem[];
    const uint32_t sbase = smem_u32(smem);
    const int tid = threadIdx.x;
    const int wid = tid >> 5;
    const int lane = tid & 31;
    const int row0 = blockIdx.y * 128;
    const int col0 = blockIdx.x * 128;
    const int nc = K >> 6;   // #chunks of 64 (>= 16 here)

#if TC_OK
    if (wid == 0) {
        TC_ALLOC(sbase, 128);
        TC_RELINQ();
    }
    if (tid == 0) {
        MBAR_INIT(sbase + 8, 1);
        MBAR_INIT(sbase + 16, 1);
        MBAR_INIT(sbase + 24, 1);
    }
    __syncthreads();
    uint32_t tmem;
    asm volatile("ld.shared.b32 %0, [%1];" : "=r"(tmem) : "r"(sbase));

    issue_chunk(sbase + 1024 + 0 * BUF_B, Ah, Al, Bh, Bl, row0, col0, K, 0,  tid);
    issue_chunk(sbase + 1024 + 1 * BUF_B, Ah, Al, Bh, Bl, row0, col0, K, 64, tid);

    uint32_t phs = 0;   // per-buffer wait parity bits
    for (int c = 0; c < nc; c++) {
        const int buf = c % 3;
        const uint32_t bufb = sbase + 1024 + buf * BUF_B;
        if (c + 1 < nc) cpasync_wait<1>(); else cpasync_wait<0>();
        asm volatile("fence.proxy.async.shared::cta;" ::: "memory");
        __syncthreads();

        if (wid == 0 && elect_one()) {
            uint64_t dAh = mk_desc(bufb + 0 * TILE_B);
            uint64_t dAl = mk_desc(bufb + 1 * TILE_B);
            uint64_t dBh = mk_desc(bufb + 2 * TILE_B);
            uint64_t dBl = mk_desc(bufb + 3 * TILE_B);
            #pragma unroll
            for (int ks = 0; ks < 4; ks++) {
                const uint64_t o = (uint64_t)(ks * 2);   // 16 bf16 = 32B = 2 units
                mma_f16_ss(tmem, dAh + o, dBh + o, IDESC_128x128, !(c == 0 && ks == 0));
                mma_f16_ss(tmem, dAh + o, dBl + o, IDESC_128x128, true);
                mma_f16_ss(tmem, dAl + o, dBh + o, IDESC_128x128, true);
            }
            TC_COMMIT(sbase + 8 + buf * 8);
        }
        if (c + 2 < nc) {
            if (c >= 1) {
                // buffer (c+2)%3 == (c-1)%3: wait its MMAs (chunk c-1) done
                const int wb = (c - 1) % 3;
                MBAR_WAIT(sbase + 8 + wb * 8, (phs >> wb) & 1);
                phs ^= (1u << wb);
            }
            issue_chunk(sbase + 1024 + ((c + 2) % 3) * BUF_B,
                        Ah, Al, Bh, Bl, row0, col0, K, (c + 2) << 6, tid);
        }
    }
    // drain the last three chunk commits (nc >= 3)
    for (int q = nc - 3; q < nc; q++) {
        const int wb = q % 3;
        MBAR_WAIT(sbase + 8 + wb * 8, (phs >> wb) & 1);
        phs ^= (1u << wb);
    }
    TC_FENCE_AFTER();

    if (wid < 4) {
        const int r = row0 + wid * 32 + lane;
        #pragma unroll
        for (int nb = 0; nb < 4; nb++) {
            uint32_t regs[32];
            TC_LD_X32(regs, tmem + nb * 32);
            TC_WAIT_LD();
            const int cb = col0 + nb * 32;
            if (EPI == 0 && GUARD == 0 && WSPLIT == 0) {
                float4* dst = reinterpret_cast<float4*>(C + (size_t)r * ldc + cb);
                #pragma unroll
                for (int j = 0; j < 8; j++) {
                    float4 v;
                    v.x = __uint_as_float(regs[4 * j + 0]);
                    v.y = __uint_as_float(regs[4 * j + 1]);
                    v.z = __uint_as_float(regs[4 * j + 2]);
                    v.w = __uint_as_float(regs[4 * j + 3]);
                    dst[j] = v;
                }
            } else {
                #pragma unroll
                for (int j = 0; j < 32; j++) {
                    const int cc = cb + j;
                    float v = __uint_as_float(regs[j]);
                    if (WSPLIT) {
                        if (cc < 32) C[(size_t)r * ldc + cc] = v;
                        const int wc = cc - 32;
                        if (wc >= 0 && (!GUARD || cc < N)) {
                            __nv_bfloat16 h = __float2bfloat16(v);
                            whi[(size_t)r * wld + wc] = h;
                            wlo[(size_t)r * wld + wc] = __float2bfloat16(v - __bfloat162float(h));
                        }
                    } else if (!GUARD || cc < N) {
                        if (EPI) v = softplusf(v + bias[cc]);
                        C[(size_t)r * ldc + cc] = v;
                    }
                }
            }
        }
        TC_FENCE_BEFORE();
    }
    __syncthreads();
    if (tid == 0) { MBAR_INVAL(sbase + 8); MBAR_INVAL(sbase + 16); MBAR_INVAL(sbase + 24); }
    __syncthreads();
    if (wid == 0) {
        TC_DEALLOC(tmem, 128);
    }
#else
    // ------------------ HMMA fallback (mma.sync m16n8k16 bf16) -------------
    const int wm = wid & 3;          // 4 warps along M (32 rows each)
    const int wn = wid >> 2;         // 2 warps along N (64 cols each)
    const int g  = lane >> 2;        // 0..7
    const int t2 = (lane & 3) * 2;   // 0,2,4,6

    float acc[2][8][4];
    #pragma unroll
    for (int mt = 0; mt < 2; mt++)
        #pragma unroll
        for (int nt = 0; nt < 8; nt++)
            #pragma unroll
            for (int j = 0; j < 4; j++) acc[mt][nt][j] = 0.0f;

    issue_chunk(sbase + 1024 + 0 * BUF_B, Ah, Al, Bh, Bl, row0, col0, K, 0,  tid);
    issue_chunk(sbase + 1024 + 1 * BUF_B, Ah, Al, Bh, Bl, row0, col0, K, 64, tid);

    for (int c = 0; c < nc; c++) {
        const uint32_t bufb = sbase + 1024 + (c % 3) * BUF_B;
        if (c + 1 < nc) cpasync_wait<1>(); else cpasync_wait<0>();
        __syncthreads();

        const uint32_t aH_t = bufb + 0 * TILE_B, aL_t = bufb + 1 * TILE_B;
        const uint32_t bH_t = bufb + 2 * TILE_B, bL_t = bufb + 3 * TILE_B;

        #pragma unroll
        for (int ks = 0; ks < 4; ks++) {
            const int kb = ks * 32 + t2 * 2;     // byte col of low k-pair
            uint32_t aH[2][4], aL[2][4], bH[8][2], bL[8][2];
            #pragma unroll
            for (int mt = 0; mt < 2; mt++) {
                const int r0 = (wm * 32 + mt * 16 + g) * 128;
                const int r1 = r0 + 8 * 128;
                aH[mt][0] = lds32(aH_t + SW(r0 + kb));
                aH[mt][1] = lds32(aH_t + SW(r1 + kb));
                aH[mt][2] = lds32(aH_t + SW(r0 + kb + 16));
                aH[mt][3] = lds32(aH_t + SW(r1 + kb + 16));
            }
            #pragma unroll
            for (int nt = 0; nt < 8; nt++) {
                const int rn = (wn * 64 + nt * 8 + g) * 128;
                bH[nt][0] = lds32(bH_t + SW(rn + kb));
                bH[nt][1] = lds32(bH_t + SW(rn + kb + 16));
            }
            #pragma unroll
            for (int mt = 0; mt < 2; mt++)
                #pragma unroll
                for (int nt = 0; nt < 8; nt++)
                    mma_bf16(acc[mt][nt], aH[mt], bH[nt]);
            #pragma unroll
            for (int nt = 0; nt < 8; nt++) {
                const int rn = (wn * 64 + nt * 8 + g) * 128;
                bL[nt][0] = lds32(bL_t + SW(rn + kb));
                bL[nt][1] = lds32(bL_t + SW(rn + kb + 16));
            }
            #pragma unroll
            for (int mt = 0; mt < 2; mt++)
                #pragma unroll
                for (int nt = 0; nt < 8; nt++)
                    mma_bf16(acc[mt][nt], aH[mt], bL[nt]);
            #pragma unroll
            for (int mt = 0; mt < 2; mt++) {
                const int r0 = (wm * 32 + mt * 16 + g) * 128;
                const int r1 = r0 + 8 * 128;
                aL[mt][0] = lds32(aL_t + SW(r0 + kb));
                aL[mt][1] = lds32(aL_t + SW(r1 + kb));
                aL[mt][2] = lds32(aL_t + SW(r0 + kb + 16));
                aL[mt][3] = lds32(aL_t + SW(r1 + kb + 16));
            }
            #pragma unroll
            for (int mt = 0; mt < 2; mt++)
                #pragma unroll
                for (int nt = 0; nt < 8; nt++)
                    mma_bf16(acc[mt][nt], aL[mt], bH[nt]);
        }
        __syncthreads();
        if (c + 2 < nc)
            issue_chunk(sbase + 1024 + ((c + 2) % 3) * BUF_B,
                        Ah, Al, Bh, Bl, row0, col0, K, (c + 2) << 6, tid);
    }

    // epilogue
    #pragma unroll
    for (int mt = 0; mt < 2; mt++) {
        const int r0 = row0 + wm * 32 + mt * 16 + g;
        const int r1 = r0 + 8;
        #pragma unroll
        for (int nt = 0; nt < 8; nt++) {
            const int c0 = col0 + wn * 64 + nt * 8 + t2;
            #pragma unroll
            for (int half = 0; half < 2; half++) {
                const int rr = half ? r1 : r0;
                #pragma unroll
                for (int q = 0; q < 2; q++) {
                    const int cc = c0 + q;
                    float v = acc[mt][nt][half * 2 + q];
                    if (WSPLIT) {
                        if (cc < 32) C[(size_t)rr * ldc + cc] = v;
                        const int wc = cc - 32;
                        if (wc >= 0 && (!GUARD || cc < N)) {
                            __nv_bfloat16 h = __float2bfloat16(v);
                            whi[(size_t)rr * wld + wc] = h;
                            wlo[(size_t)rr * wld + wc] = __float2bfloat16(v - __bfloat162float(h));
                        }
                    } else if (!GUARD || cc < N) {
                        if (EPI) v = softplusf(v + bias[cc]);
                        C[(size_t)rr * ldc + cc] = v;
                    }
                }
            }
        }
    }
#endif
}

// ---------------------------------------------------------------------------
// fp32 -> bf16 hi/lo split for x (GEMM1 A operand)
// ---------------------------------------------------------------------------
__global__ void split_a_kernel(const float* __restrict__ src,
                               __nv_bfloat16* __restrict__ hi,
                               __nv_bfloat16* __restrict__ lo, int total)
{
    int idx = blockIdx.x * blockDim.x + threadIdx.x;
    if (idx >= total) return;
    float v = src[idx];
    __nv_bfloat16 h = __float2bfloat16(v);
    hi[idx] = h;
    lo[idx] = __float2bfloat16(v - __bfloat162float(h));
}

// ---------------------------------------------------------------------------
// W [K,N] row-major -> W^T [Npad,K] bf16 hi/lo (zero-padded rows N..Npad)
// ---------------------------------------------------------------------------
__global__ void split_w_kernel(const float* __restrict__ W, int K, int N, int Npad,
                               __nv_bfloat16* __restrict__ hi,
                               __nv_bfloat16* __restrict__ lo)
{
    __shared__ float t[32][33];
    const int n0 = blockIdx.x * 32, k0 = blockIdx.y * 32;
    const int tx = threadIdx.x, ty = threadIdx.y;
    const int n = n0 + tx, k = k0 + ty;
    t[ty][tx] = (n < N) ? W[(size_t)k * N + n] : 0.0f;
    __syncthreads();
    const int on = n0 + ty, ok = k0 + tx;
    float v = t[tx][ty];
    __nv_bfloat16 h = __float2bfloat16(v);
    hi[(size_t)on * K + ok] = h;
    lo[(size_t)on * K + ok] = __float2bfloat16(v - __bfloat162float(h));
}

// ---------------------------------------------------------------------------
// Causal depthwise conv (k=4) + bias + silu : g_xz[:, :DI] -> g_u (+ hi/lo)
// ---------------------------------------------------------------------------
__global__ void conv_silu_kernel(const float* __restrict__ conv_w,
                                 const float* __restrict__ conv_b,
                                 __nv_bfloat16* __restrict__ uhi,
                                 __nv_bfloat16* __restrict__ ulo)
{
    int idx = blockIdx.x * blockDim.x + threadIdx.x;
    if (idx >= MR * DI) return;
    int d = idx & (DI - 1);
    int row = idx >> 11;
    int l = row & (LL - 1);
    int b = row >> 10;

    float acc = conv_b[d];
    #pragma unroll
    for (int j = 0; j < DC; j++) {
        int ll = l - (DC - 1) + j;
        if (ll >= 0) {
            acc = fmaf(g_xz[(size_t)(b * LL + ll) * NXZ + d], conv_w[d * DC + j], acc);
        }
    }
    float v = siluf(acc);
    g_u[idx] = v;
    __nv_bfloat16 h = __float2bfloat16(v);
    uhi[idx] = h;
    ulo[idx] = __float2bfloat16(v - __bfloat162float(h));
}

// ---------------------------------------------------------------------------
// Chunked selective scan, pass 1: per-chunk local scan (zero init).
// thread t: n=t&15, ch=(t>>4)&15, d=(t>>8)&2047, b=t>>19.
// Stores chunk-final h and decay product P = exp(An * sum(dt)).
// ---------------------------------------------------------------------------
__global__ void scan_pass1(const float* __restrict__ A_log)
{
    int t = blockIdx.x * blockDim.x + threadIdx.x;
    int n  = t & (DS - 1);
    int ch = (t >> 4) & (NCH - 1);
    int d  = (t >> 8) & (DI - 1);
    int b  = t >> 19;

    const float An = -__expf(A_log[d * DS + n]);
    const int l0 = ch * CHL;

    const float* dt_p = g_dt + ((size_t)b * LL + l0) * DI + d;
    const float* u_p  = g_u  + ((size_t)b * LL + l0) * DI + d;
    const float* bc_p = g_ssm + ((size_t)b * LL + l0) * NSSM;

    float h = 0.0f, S = 0.0f;
    #pragma unroll 4
    for (int l = 0; l < CHL; l++) {
        float dt_v = dt_p[(size_t)l * DI];
        float u_v  = u_p [(size_t)l * DI];
        float Bv   = bc_p[(size_t)l * NSSM + n];
        h = fmaf(__expf(dt_v * An), h, dt_v * Bv * u_v);
        S += dt_v;
    }
    const size_t idx = (((size_t)b * DI + d) * NCH + ch) * DS + n;
    g_hfin[idx] = h;
    g_P[idx]    = __expf(An * S);
}

// ---------------------------------------------------------------------------
// Pass 2: combine chunk states serially (16 steps). thread per (b,d,n).
// g_hfin becomes INCLUSIVE prefix state at chunk ends.
// ---------------------------------------------------------------------------
__global__ void scan_pass2()
{
    int t = blockIdx.x * blockDim.x + threadIdx.x;
    int n = t & (DS - 1);
    int d = (t >> 4) & (DI - 1);
    int b = t >> 15;

    const size_t base = ((size_t)b * DI + d) * NCH * DS + n;
    float H = 0.0f;
    #pragma unroll
    for (int ch = 0; ch < NCH; ch++) {
        const size_t idx = base + (size_t)ch * DS;
        H = fmaf(g_P[idx], H, g_hfin[idx]);
        g_hfin[idx] = H;
    }
}

// ---------------------------------------------------------------------------
// Pass 3: replay chunks from combined prefixes, emit y. Same layout as pass1.
// ---------------------------------------------------------------------------
__global__ void scan_pass3(const float* __restrict__ A_log)
{
    int t = blockIdx.x * blockDim.x + threadIdx.x;
    int n  = t & (DS - 1);
    int ch = (t >> 4) & (NCH - 1);
    int d  = (t >> 8) & (DI - 1);
    int b  = t >> 19;

    const float An = -__expf(A_log[d * DS + n]);
    const int l0 = ch * CHL;

    const float* dt_p = g_dt + ((size_t)b * LL + l0) * DI + d;
    const float* u_p  = g_u  + ((size_t)b * LL + l0) * DI + d;
    const float* bc_p = g_ssm + ((size_t)b * LL + l0) * NSSM;
    float* y_p = g_y + ((size_t)b * LL + l0) * DI + d;

    float h = 0.0f;
    if (ch > 0)
        h = g_hfin[(((size_t)b * DI + d) * NCH + (ch - 1)) * DS + n];

    #pragma unroll 4
    for (int l = 0; l < CHL; l++) {
        float dt_v = dt_p[(size_t)l * DI];
        float u_v  = u_p [(size_t)l * DI];
        float Bv   = bc_p[(size_t)l * NSSM + n];
        float Cv   = bc_p[(size_t)l * NSSM + DS + n];
        h = fmaf(__expf(dt_v * An), h, dt_v * Bv * u_v);
        float p = h * Cv;
        p += __shfl_xor_sync(0xffffffffu, p, 8);
        p += __shfl_xor_sync(0xffffffffu, p, 4);
        p += __shfl_xor_sync(0xffffffffu, p, 2);
        p += __shfl_xor_sync(0xffffffffu, p, 1);
        if (n == 0) y_p[(size_t)l * DI] = p;
    }
}

// ---------------------------------------------------------------------------
// Gate: out_a = split((y + D[d]*u) * silu(z))  (bf16 hi/lo for GEMM4)
// ---------------------------------------------------------------------------
__global__ void gate_kernel(const float* __restrict__ Dvec,
                            __nv_bfloat16* __restrict__ hi,
                            __nv_bfloat16* __restrict__ lo)
{
    int idx = blockIdx.x * blockDim.x + threadIdx.x;
    if (idx >= MR * DI) return;
    int d = idx & (DI - 1);
    int row = idx >> 11;
    float z = g_xz[(size_t)row * NXZ + DI + d];
    float v = fmaf(Dvec[d], g_u[idx], g_y[idx]) * siluf(z);
    __nv_bfloat16 h = __float2bfloat16(v);
    hi[idx] = h;
    lo[idx] = __float2bfloat16(v - __bfloat162float(h));
}

// ---------------------------------------------------------------------------
extern "C" void kernel_launch(void* const* d_in, const int* in_sizes, int n_in,
                              void* d_out, int out_size)
{
    const float* x         = (const float*)d_in[0];
    const float* in_proj_w = (const float*)d_in[1];
    const float* conv_w    = (const float*)d_in[2];
    const float* conv_b    = (const float*)d_in[3];
    const float* x_proj_w  = (const float*)d_in[4];
    const float* dt_proj_w = (const float*)d_in[5];
    const float* dt_proj_b = (const float*)d_in[6];
    const float* A_log     = (const float*)d_in[7];
    const float* Dvec      = (const float*)d_in[8];
    const float* out_proj_w= (const float*)d_in[9];
    float* out = (float*)d_out;

    float* xz;  cudaGetSymbolAddress((void**)&xz,  g_xz);
    float* u;   cudaGetSymbolAddress((void**)&u,   g_u);
    float* ssm; cudaGetSymbolAddress((void**)&ssm, g_ssm);
    float* dt;  cudaGetSymbolAddress((void**)&dt,  g_dt);
    __nv_bfloat16 *ah, *al, *bh, *bl, *ch, *cl;
    cudaGetSymbolAddress((void**)&ah, g_ah);
    cudaGetSymbolAddress((void**)&al, g_al);
    cudaGetSymbolAddress((void**)&bh, g_bh);
    cudaGetSymbolAddress((void**)&bl, g_bl);
    cudaGetSymbolAddress((void**)&ch, g_ch);
    cudaGetSymbolAddress((void**)&cl, g_cl);

    cudaFuncSetAttribute(gemm_tc<0,0,0>, cudaFuncAttributeMaxDynamicSharedMemorySize, SMEM_TOTAL);
    cudaFuncSetAttribute(gemm_tc<0,1,1>, cudaFuncAttributeMaxDynamicSharedMemorySize, SMEM_TOTAL);
    cudaFuncSetAttribute(gemm_tc<1,0,0>, cudaFuncAttributeMaxDynamicSharedMemorySize, SMEM_TOTAL);

    dim3 blk(256);
    dim3 tblk(32, 32);

    // ---- GEMM1: xz = x @ in_proj_w   [2048,1024]@[1024,4096] ----
    split_a_kernel<<<(MR * DM + 255) / 256, blk>>>(x, ah, al, MR * DM);
    split_w_kernel<<<dim3(NXZ / 32, DM / 32), tblk>>>(in_proj_w, DM, NXZ, NXZ, bh, bl);
    gemm_tc<0,0,0><<<dim3(NXZ / 128, MR / 128), blk, SMEM_TOTAL>>>(
        ah, al, bh, bl, xz, NXZ, NXZ, DM, nullptr, nullptr, nullptr, 0);

    // ---- conv + silu -> u (fp32 + bf16 hi/lo) ----
    conv_silu_kernel<<<(MR * DI + 255) / 256, blk>>>(conv_w, conv_b, ah, al);

    // ---- GEMM2: ssm = u @ x_proj_w; cols>=32 split into g_ch/g_cl ----
    split_w_kernel<<<dim3(NSSM_PAD / 32, DI / 32), tblk>>>(x_proj_w, DI, NSSM, NSSM_PAD, bh, bl);
    gemm_tc<0,1,1><<<dim3(NSSM_PAD / 128, MR / 128), blk, SMEM_TOTAL>>>(
        ah, al, bh, bl, ssm, NSSM, NSSM, DI, nullptr, ch, cl, DI);

    // ---- GEMM3: dt = softplus(dt_in @ dt_proj_w + b) ----
    split_w_kernel<<<dim3(DI / 32, DI / 32), tblk>>>(dt_proj_w, DI, DI, DI, bh, bl);
    gemm_tc<1,0,0><<<dim3(DI / 128, MR / 128), blk, SMEM_TOTAL>>>(
        ch, cl, bh, bl, dt, DI, DI, DI, dt_proj_b, nullptr, nullptr, 0);

    // ---- chunked selective scan -> g_y ----
    scan_pass1<<<(BB * DI * NCH * DS) / 256, blk>>>(A_log);
    scan_pass2<<<(BB * DI * DS) / 256, blk>>>();
    scan_pass3<<<(BB * DI * NCH * DS) / 256, blk>>>(A_log);

    // ---- gate -> bf16 hi/lo (GEMM4 A operand) ----
    gate_kernel<<<(MR * DI + 255) / 256, blk>>>(Dvec, ah, al);

    // ---- GEMM4: out = gated @ out_proj_w  [2048,2048]@[2048,1024] ----
    split_w_kernel<<<dim3(DM / 32, DI / 32), tblk>>>(out_proj_w, DI, DM, DM, bh, bl);
    gemm_tc<0,0,0><<<dim3(DM / 128, MR / 128), blk, SMEM_TOTAL>>>(
        ah, al, bh, bl, out, DM, DM, DI, nullptr, nullptr, nullptr, 0);
}